// round 3
// baseline (speedup 1.0000x reference)
#include <cuda_runtime.h>

// Problem constants (fixed by the reference):
//   B=32768 rows, F=32 factors, U=256 outputs.
// out[b,u] = prod_f(in[b,f]*w[f,u]) + bias[u] = P[b]*W[u] + bias[u]
static constexpr int Bn = 32768;
static constexpr int Fn = 32;
static constexpr int Un = 256;
static constexpr int ROWS_PER_BLOCK = 8;

// Scratch for the 256 column products (no cudaMalloc allowed).
__device__ float g_W[Un];

// Kernel 1: W[u] = prod_f w[f,u].  One block of 256 threads; trivial cost.
__global__ void colprod_kernel(const float* __restrict__ w) {
    int u = threadIdx.x;
    float p = 1.0f;
#pragma unroll
    for (int f = 0; f < Fn; ++f) {
        p *= w[f * Un + u];   // coalesced across threads for each f
    }
    g_W[u] = p;
}

// Kernel 2: stream the rank-1 outer product.
// Block = 256 threads, handles 8 rows:
//   - threads 0..63 load the 8x32 input tile as float4 (one float4 each),
//     multiply 4 elements, then shfl-reduce within 8-lane groups -> P[row]
//   - all 256 threads write 8 rows x 256 cols = 512 float4 stores (2 each)
__global__ __launch_bounds__(256)
void outer_kernel(const float* __restrict__ in,
                  const float* __restrict__ bias,
                  float* __restrict__ out) {
    __shared__ float sW[Un];
    __shared__ float sB[Un];
    __shared__ float sP[ROWS_PER_BLOCK];

    const int t = threadIdx.x;
    sW[t] = g_W[t];
    sB[t] = bias[t];

    const long long row0 = (long long)blockIdx.x * ROWS_PER_BLOCK;

    if (t < 64) {  // warps 0 and 1 (full warps -> safe full-mask shuffles)
        const float4* in4 = reinterpret_cast<const float4*>(in + row0 * Fn);
        float4 v = in4[t];                       // 8 rows * 32 f = 64 float4
        float p = v.x * v.y * v.z * v.w;
        // reduce product across the 8 lanes covering one row (8 float4 = 32 f)
        p *= __shfl_xor_sync(0xffffffffu, p, 1);
        p *= __shfl_xor_sync(0xffffffffu, p, 2);
        p *= __shfl_xor_sync(0xffffffffu, p, 4);
        if ((t & 7) == 0) sP[t >> 3] = p;
    }
    __syncthreads();

    float4* out4 = reinterpret_cast<float4*>(out + row0 * Un);
    const float4* sW4 = reinterpret_cast<const float4*>(sW);
    const float4* sB4 = reinterpret_cast<const float4*>(sB);

#pragma unroll
    for (int i = 0; i < 2; ++i) {
        const int idx = i * 256 + t;   // float4 index within this block's 8 rows
        const int r = idx >> 6;        // 64 float4 per row
        const int c = idx & 63;
        const float p = sP[r];
        const float4 wv = sW4[c];
        const float4 bv = sB4[c];
        float4 o;
        o.x = fmaf(p, wv.x, bv.x);
        o.y = fmaf(p, wv.y, bv.y);
        o.z = fmaf(p, wv.z, bv.z);
        o.w = fmaf(p, wv.w, bv.w);
        out4[idx] = o;                 // fully coalesced 128B stores per warp
    }
}

extern "C" void kernel_launch(void* const* d_in, const int* in_sizes, int n_in,
                              void* d_out, int out_size) {
    // metadata order: inputs [B,F], weight [F,U], weight_selector [F,U] (dead), bias [U]
    const float* in   = (const float*)d_in[0];
    const float* w    = (const float*)d_in[1];
    const float* bias = (const float*)d_in[3];
    float* out        = (float*)d_out;

    colprod_kernel<<<1, Un>>>(w);
    outer_kernel<<<Bn / ROWS_PER_BLOCK, 256>>>(in, bias, out);
}